// round 8
// baseline (speedup 1.0000x reference)
#include <cuda_runtime.h>
#include <cuda_bf16.h>
#include <cstdint>

#define MAX_B  32768
#define H      64
#define TPB    256          // 8 warps = 8 batch groups per block
#define NT     5            // targets batched per half-warp (covers tsz<=10)

__device__ int g_soff[MAX_B];
__device__ int g_toff[MAX_B];

// ---------------------------------------------------------------------------
// Kernel 1: exclusive scan, 16384 per tile (16 elems/thread).
// ---------------------------------------------------------------------------
__global__ void __launch_bounds__(1024)
scan_kernel(const int* __restrict__ size, const int* __restrict__ tsize, int B) {
    __shared__ int sw[32], tw[32];
    const int t = threadIdx.x, lane = t & 31, wid = t >> 5;
    int cs = 0, ct = 0;

    for (int base = 0; base < B; base += 16384) {
        const int e0 = base + t * 16;
        int sv[16], tv[16];
        #pragma unroll
        for (int j = 0; j < 16; j += 4) {
            int4 a = make_int4(0,0,0,0), c = make_int4(0,0,0,0);
            if (e0 + j + 3 < B) {
                a = *(const int4*)(size  + e0 + j);
                c = *(const int4*)(tsize + e0 + j);
            } else {
                if (e0+j   < B) { a.x = size[e0+j];   c.x = tsize[e0+j]; }
                if (e0+j+1 < B) { a.y = size[e0+j+1]; c.y = tsize[e0+j+1]; }
                if (e0+j+2 < B) { a.z = size[e0+j+2]; c.z = tsize[e0+j+2]; }
            }
            sv[j]=a.x; sv[j+1]=a.y; sv[j+2]=a.z; sv[j+3]=a.w;
            tv[j]=c.x; tv[j+1]=c.y; tv[j+2]=c.z; tv[j+3]=c.w;
        }
        int s_tot = 0, t_tot = 0;
        #pragma unroll
        for (int j = 0; j < 16; j++) { s_tot += sv[j]; t_tot += tv[j]; }

        int si = s_tot, ti = t_tot;
        #pragma unroll
        for (int o = 1; o < 32; o <<= 1) {
            int a = __shfl_up_sync(0xffffffffu, si, o);
            int b = __shfl_up_sync(0xffffffffu, ti, o);
            if (lane >= o) { si += a; ti += b; }
        }
        if (lane == 31) { sw[wid] = si; tw[wid] = ti; }
        __syncthreads();
        if (wid == 0) {
            int a = sw[lane], b = tw[lane];
            #pragma unroll
            for (int o = 1; o < 32; o <<= 1) {
                int x = __shfl_up_sync(0xffffffffu, a, o);
                int y = __shfl_up_sync(0xffffffffu, b, o);
                if (lane >= o) { a += x; b += y; }
            }
            sw[lane] = a; tw[lane] = b;
        }
        __syncthreads();

        int ps = cs + (wid ? sw[wid-1] : 0) + si - s_tot;
        int pt = ct + (wid ? tw[wid-1] : 0) + ti - t_tot;
        #pragma unroll
        for (int j = 0; j < 16; j += 4) {
            int4 os, ot;
            os.x = ps;             ot.x = pt;
            os.y = ps + sv[j];     ot.y = pt + tv[j];
            os.z = os.y + sv[j+1]; ot.z = ot.y + tv[j+1];
            os.w = os.z + sv[j+2]; ot.w = ot.z + tv[j+2];
            if (e0 + j + 3 < B) {
                *(int4*)(g_soff + e0 + j) = os;
                *(int4*)(g_toff + e0 + j) = ot;
            } else {
                if (e0+j   < B) { g_soff[e0+j]   = os.x; g_toff[e0+j]   = ot.x; }
                if (e0+j+1 < B) { g_soff[e0+j+1] = os.y; g_toff[e0+j+1] = ot.y; }
                if (e0+j+2 < B) { g_soff[e0+j+2] = os.z; g_toff[e0+j+2] = ot.z; }
            }
            ps = os.w + sv[j+3]; pt = ot.w + tv[j+3];
        }
        cs += sw[31]; ct += tw[31];
        __syncthreads();
    }
}

__device__ __forceinline__ float4 f4add(float4 a, float4 b) {
    return make_float4(a.x + b.x, a.y + b.y, a.z + b.z, a.w + b.w);
}
__device__ __forceinline__ int pick_idx(int ia, int ib, int r) {
    const int v = __shfl_sync(0xffffffffu, ia, r & 31);
    const int w = __shfl_sync(0xffffffffu, ib, r & 31);
    return (r < 32) ? v : w;
}
template <int N>
__device__ __forceinline__ void red16(float (&v)[N]) {
    #pragma unroll
    for (int o = 8; o > 0; o >>= 1) {
        #pragma unroll
        for (int k = 0; k < N; k++)
            v[k] += __shfl_xor_sync(0xffffffffu, v[k], o);
    }
}

// ---------------------------------------------------------------------------
// Kernel 2: one warp per batch group (R4 item loop). PDL: starts before the
// scan finishes; grid-dependency sync guards the offset reads. Targets are
// batched into one load wave + one red16<15>.
// ---------------------------------------------------------------------------
__global__ void __launch_bounds__(TPB, 7)
simplex_kernel(const int*   __restrict__ user,
               const int*   __restrict__ item,
               const int*   __restrict__ tgt,
               const int*   __restrict__ size,
               const int*   __restrict__ tsize,
               const float* __restrict__ uw,
               const float* __restrict__ iw,
               float*       __restrict__ out,
               int B) {
    const int b = blockIdx.x * (TPB >> 5) + (threadIdx.x >> 5);
    if (b >= B) return;
    const int lane = threadIdx.x & 31;
    const int q    = lane & 15;
    const int h    = lane >> 4;

    // pre-sync work (independent of the scan results)
    const int sz  = __ldg(&size[b]);
    const int tsz = __ldg(&tsize[b]);

    cudaGridDependencySynchronize();   // scan results now visible

    const int soff = g_soff[b];
    const int toff = g_toff[b];

    // prefetch scalar indices early (ride through the item loop)
    const int nt0  = min(tsz, 2 * NT);
    const int ta   = (lane < min(tsz, 32)) ? __ldg(&tgt[toff + lane]) : 0;
    const int ui   = max(soff + sz - 1, 0);
    const int urow = __ldg(&user[ui]);

    // ---- item segment sum: chunks of 64 indices, 16 rows / 8 loads per iter
    float4 acc0 = make_float4(0.f,0.f,0.f,0.f);
    float4 acc1 = make_float4(0.f,0.f,0.f,0.f);
    for (int cb = 0; cb < sz; cb += 64) {
        const int n  = min(sz - cb, 64);
        const int ia = (lane      < n) ? __ldg(&item[soff + cb + lane])      : 0;
        const int ib = (lane + 32 < n) ? __ldg(&item[soff + cb + 32 + lane]) : 0;

        int base = 0;
        for (; base + 8 <= n; base += 8) {
            const int i0 = pick_idx(ia, ib, base + 0 + h);
            const int i1 = pick_idx(ia, ib, base + 2 + h);
            const int i2 = pick_idx(ia, ib, base + 4 + h);
            const int i3 = pick_idx(ia, ib, base + 6 + h);
            const float4 v0 = __ldg((const float4*)&iw[(size_t)i0 * H + 4 * q]);
            const float4 v1 = __ldg((const float4*)&iw[(size_t)i1 * H + 4 * q]);
            const float4 v2 = __ldg((const float4*)&iw[(size_t)i2 * H + 4 * q]);
            const float4 v3 = __ldg((const float4*)&iw[(size_t)i3 * H + 4 * q]);
            acc0 = f4add(acc0, f4add(v0, v2));
            acc1 = f4add(acc1, f4add(v1, v3));
        }
        for (; base < n; base += 2) {
            const int r = base + h;
            if (r < n) {
                const int ii = pick_idx(ia, ib, r);
                acc0 = f4add(acc0, __ldg((const float4*)&iw[(size_t)ii * H + 4 * q]));
            }
        }
    }

    // ---- issue user + all target row loads NOW (overlap with epilogue math)
    const float4 ue = __ldg((const float4*)&uw[(size_t)urow * H + 4 * q]);
    float4 tr[NT];
    #pragma unroll
    for (int k = 0; k < NT; k++) {
        const int t   = 2 * k + h;
        const int row = __shfl_sync(0xffffffffu, ta, t & 31);
        tr[k] = (t < nt0) ? __ldg((const float4*)&iw[(size_t)row * H + 4 * q])
                          : make_float4(0.f, 0.f, 0.f, 0.f);
    }

    float4 acc = f4add(acc0, acc1);
    acc.x += __shfl_xor_sync(0xffffffffu, acc.x, 16);
    acc.y += __shfl_xor_sync(0xffffffffu, acc.y, 16);
    acc.z += __shfl_xor_sync(0xffffffffu, acc.z, 16);
    acc.w += __shfl_xor_sync(0xffffffffu, acc.w, 16);

    // ---- emb = 0.5*user + 0.5*mean ----
    const float inv = 0.5f / ((float)sz + 1e-6f);
    float4 emb;
    emb.x = 0.5f * ue.x + acc.x * inv;
    emb.y = 0.5f * ue.y + acc.y * inv;
    emb.z = 0.5f * ue.z + acc.z * inv;
    emb.w = 0.5f * ue.w + acc.w * inv;

    // ---- center + L2 normalize (width-16, replicated in both halves) ----
    float v2r[2];
    v2r[0] = emb.x + emb.y + emb.z + emb.w;
    v2r[1] = emb.x*emb.x + emb.y*emb.y + emb.z*emb.z + emb.w*emb.w;
    red16<2>(v2r);
    const float mean = v2r[0] * (1.0f / H);
    const float ss   = fmaxf(v2r[1] - v2r[0] * mean, 0.0f);
    const float invn = 1.0f / fmaxf(sqrtf(ss), 1e-12f);
    float4 en;
    en.x = (emb.x - mean) * invn;
    en.y = (emb.y - mean) * invn;
    en.z = (emb.z - mean) * invn;
    en.w = (emb.w - mean) * invn;

    // ---- targets: one batched reduction. sum(en)==0 so
    //      dot(center(te), en) == dot(te, en). ----
    float r3[3 * NT];
    #pragma unroll
    for (int k = 0; k < NT; k++) {
        const float4 te = tr[k];
        r3[3*k+0] = te.x + te.y + te.z + te.w;
        r3[3*k+1] = te.x*te.x + te.y*te.y + te.z*te.z + te.w*te.w;
        r3[3*k+2] = te.x*en.x + te.y*en.y + te.z*en.z + te.w*en.w;
    }
    red16<3 * NT>(r3);
    if (q == 0) {
        #pragma unroll
        for (int k = 0; k < NT; k++) {
            const int t = 2 * k + h;
            if (t < nt0) {
                const float mt  = r3[3*k+0] * (1.0f / H);
                const float sst = fmaxf(r3[3*k+1] - r3[3*k+0] * mt, 0.0f);
                out[toff + t] = r3[3*k+2] / fmaxf(sqrtf(sst), 1e-12f);
            }
        }
    }
    // rare fallback: tsz > 10
    for (int t0 = 2 * NT; t0 < tsz; t0 += 2) {
        const int t = t0 + h;
        if (t < tsz) {
            const int row = __ldg(&tgt[toff + t]);
            const float4 te = __ldg((const float4*)&iw[(size_t)row * H + 4 * q]);
            float v3[3];
            v3[0] = te.x + te.y + te.z + te.w;
            v3[1] = te.x*te.x + te.y*te.y + te.z*te.z + te.w*te.w;
            v3[2] = te.x*en.x + te.y*en.y + te.z*en.z + te.w*en.w;
            red16<3>(v3);
            if (q == 0) {
                const float mt  = v3[0] * (1.0f / H);
                const float sst = fmaxf(v3[1] - v3[0] * mt, 0.0f);
                out[toff + t] = v3[2] / fmaxf(sqrtf(sst), 1e-12f);
            }
        }
    }
}

// ---------------------------------------------------------------------------
extern "C" void kernel_launch(void* const* d_in, const int* in_sizes, int n_in,
                              void* d_out, int out_size) {
    const int*   user        = (const int*)d_in[0];
    const int*   item        = (const int*)d_in[1];
    const int*   target_item = (const int*)d_in[2];
    const int*   size        = (const int*)d_in[3];
    const int*   target_size = (const int*)d_in[4];
    const float* user_weight = (const float*)d_in[5];
    const float* item_weight = (const float*)d_in[6];
    float*       out         = (float*)d_out;

    const int B = in_sizes[3];
    const int wpb  = TPB >> 5;
    const int grid = (B + wpb - 1) / wpb;

    scan_kernel<<<1, 1024>>>(size, target_size, B);

    // PDL launch: main kernel overlaps the scan's tail + launch latency.
    cudaLaunchConfig_t cfg = {};
    cfg.gridDim  = dim3((unsigned)grid);
    cfg.blockDim = dim3(TPB);
    cudaLaunchAttribute attr[1];
    attr[0].id = cudaLaunchAttributeProgrammaticStreamSerialization;
    attr[0].val.programmaticStreamSerializationAllowed = 1;
    cfg.attrs    = attr;
    cfg.numAttrs = 1;
    cudaLaunchKernelEx(&cfg, simplex_kernel,
                       user, item, target_item, size, target_size,
                       user_weight, item_weight, out, B);
}

// round 10
// speedup vs baseline: 1.0404x; 1.0404x over previous
#include <cuda_runtime.h>
#include <cuda_bf16.h>
#include <cstdint>

#define MAX_B  32768
#define H      64
#define TPB    256          // 8 warps = 8 batch groups per block
#define NT     5            // targets prefetched per half-warp (covers tsz<=10)

__device__ int g_soff[MAX_B];
__device__ int g_toff[MAX_B];

// ---------------------------------------------------------------------------
// Kernel 1: exclusive scan, 16384 per tile (16 elems/thread).
// ---------------------------------------------------------------------------
__global__ void __launch_bounds__(1024)
scan_kernel(const int* __restrict__ size, const int* __restrict__ tsize, int B) {
    __shared__ int sw[32], tw[32];
    const int t = threadIdx.x, lane = t & 31, wid = t >> 5;
    int cs = 0, ct = 0;

    for (int base = 0; base < B; base += 16384) {
        const int e0 = base + t * 16;
        int sv[16], tv[16];
        #pragma unroll
        for (int j = 0; j < 16; j += 4) {
            int4 a = make_int4(0,0,0,0), c = make_int4(0,0,0,0);
            if (e0 + j + 3 < B) {
                a = *(const int4*)(size  + e0 + j);
                c = *(const int4*)(tsize + e0 + j);
            } else {
                if (e0+j   < B) { a.x = size[e0+j];   c.x = tsize[e0+j]; }
                if (e0+j+1 < B) { a.y = size[e0+j+1]; c.y = tsize[e0+j+1]; }
                if (e0+j+2 < B) { a.z = size[e0+j+2]; c.z = tsize[e0+j+2]; }
            }
            sv[j]=a.x; sv[j+1]=a.y; sv[j+2]=a.z; sv[j+3]=a.w;
            tv[j]=c.x; tv[j+1]=c.y; tv[j+2]=c.z; tv[j+3]=c.w;
        }
        int s_tot = 0, t_tot = 0;
        #pragma unroll
        for (int j = 0; j < 16; j++) { s_tot += sv[j]; t_tot += tv[j]; }

        int si = s_tot, ti = t_tot;
        #pragma unroll
        for (int o = 1; o < 32; o <<= 1) {
            int a = __shfl_up_sync(0xffffffffu, si, o);
            int b = __shfl_up_sync(0xffffffffu, ti, o);
            if (lane >= o) { si += a; ti += b; }
        }
        if (lane == 31) { sw[wid] = si; tw[wid] = ti; }
        __syncthreads();
        if (wid == 0) {
            int a = sw[lane], b = tw[lane];
            #pragma unroll
            for (int o = 1; o < 32; o <<= 1) {
                int x = __shfl_up_sync(0xffffffffu, a, o);
                int y = __shfl_up_sync(0xffffffffu, b, o);
                if (lane >= o) { a += x; b += y; }
            }
            sw[lane] = a; tw[lane] = b;
        }
        __syncthreads();

        int ps = cs + (wid ? sw[wid-1] : 0) + si - s_tot;
        int pt = ct + (wid ? tw[wid-1] : 0) + ti - t_tot;
        #pragma unroll
        for (int j = 0; j < 16; j += 4) {
            int4 os, ot;
            os.x = ps;             ot.x = pt;
            os.y = ps + sv[j];     ot.y = pt + tv[j];
            os.z = os.y + sv[j+1]; ot.z = ot.y + tv[j+1];
            os.w = os.z + sv[j+2]; ot.w = ot.z + tv[j+2];
            if (e0 + j + 3 < B) {
                *(int4*)(g_soff + e0 + j) = os;
                *(int4*)(g_toff + e0 + j) = ot;
            } else {
                if (e0+j   < B) { g_soff[e0+j]   = os.x; g_toff[e0+j]   = ot.x; }
                if (e0+j+1 < B) { g_soff[e0+j+1] = os.y; g_toff[e0+j+1] = ot.y; }
                if (e0+j+2 < B) { g_soff[e0+j+2] = os.z; g_toff[e0+j+2] = ot.z; }
            }
            ps = os.w + sv[j+3]; pt = ot.w + tv[j+3];
        }
        cs += sw[31]; ct += tw[31];
        __syncthreads();
    }
}

// ---------------------------------------------------------------------------
// helpers
// ---------------------------------------------------------------------------
__device__ __forceinline__ float4 f4add(float4 a, float4 b) {
    return make_float4(a.x + b.x, a.y + b.y, a.z + b.z, a.w + b.w);
}
__device__ __forceinline__ int pick_idx(int ia, int ib, int r) {
    const int v = __shfl_sync(0xffffffffu, ia, r & 31);
    const int w = __shfl_sync(0xffffffffu, ib, r & 31);
    return (r < 32) ? v : w;
}
template <int N>
__device__ __forceinline__ void red16(float (&v)[N]) {
    #pragma unroll
    for (int o = 8; o > 0; o >>= 1) {
        #pragma unroll
        for (int k = 0; k < N; k++)
            v[k] += __shfl_xor_sync(0xffffffffu, v[k], o);
    }
}
// L2 retain-bias policy (evict_last, fraction 1.0)
__device__ __forceinline__ uint64_t mk_policy() {
    uint64_t pol;
    asm("createpolicy.fractional.L2::evict_last.b64 %0, 1.0;" : "=l"(pol));
    return pol;
}
// embedding-row gather with cache-hint (second touches should hit L2)
__device__ __forceinline__ float4 ldg_el(const float* p, uint64_t pol) {
    float4 v;
    asm("ld.global.nc.L2::cache_hint.v4.f32 {%0,%1,%2,%3}, [%4], %5;"
        : "=f"(v.x), "=f"(v.y), "=f"(v.z), "=f"(v.w) : "l"(p), "l"(pol));
    return v;
}

// ---------------------------------------------------------------------------
// Kernel 2 (R4 structure): one warp per batch group; 16 lanes/row (quad q),
// halves h=0/1. Item phase: 8 independent gathers/lane/iter (16 rows/warp).
// Target phase: one wave of <=5 loads per lane + one batched reduction.
// ---------------------------------------------------------------------------
__global__ void __launch_bounds__(TPB, 8)
simplex_kernel(const int*   __restrict__ user,
               const int*   __restrict__ item,
               const int*   __restrict__ tgt,
               const int*   __restrict__ size,
               const int*   __restrict__ tsize,
               const float* __restrict__ uw,
               const float* __restrict__ iw,
               float*       __restrict__ out,
               int B) {
    const int b = blockIdx.x * (TPB >> 5) + (threadIdx.x >> 5);
    if (b >= B) return;
    const int lane = threadIdx.x & 31;
    const int q    = lane & 15;
    const int h    = lane >> 4;
    const uint64_t pol = mk_policy();

    const int soff = g_soff[b];
    const int toff = g_toff[b];
    const int sz   = size[b];
    const int tsz  = tsize[b];

    // ---- item segment sum: chunks of 64 indices, 16 rows per iteration ----
    float4 acc0 = make_float4(0.f,0.f,0.f,0.f);
    float4 acc1 = make_float4(0.f,0.f,0.f,0.f);
    for (int cb = 0; cb < sz; cb += 64) {
        const int n  = min(sz - cb, 64);
        const int ia = (lane      < n) ? __ldg(&item[soff + cb + lane])      : 0;
        const int ib = (lane + 32 < n) ? __ldg(&item[soff + cb + 32 + lane]) : 0;

        int base = 0;
        for (; base + 16 <= n; base += 16) {
            int idx[8];
            #pragma unroll
            for (int j = 0; j < 8; j++) idx[j] = pick_idx(ia, ib, base + 2*j + h);
            float4 v[8];
            #pragma unroll
            for (int j = 0; j < 8; j++)
                v[j] = ldg_el(&iw[(size_t)idx[j] * H + 4 * q], pol);
            acc0 = f4add(acc0, f4add(f4add(v[0], v[2]), f4add(v[4], v[6])));
            acc1 = f4add(acc1, f4add(f4add(v[1], v[3]), f4add(v[5], v[7])));
        }
        for (; base < n; base += 2) {
            const int r = base + h;
            if (r < n) {
                const int ii = pick_idx(ia, ib, r);
                acc0 = f4add(acc0, ldg_el(&iw[(size_t)ii * H + 4 * q], pol));
            }
        }
    }
    float4 acc = f4add(acc0, acc1);
    acc.x += __shfl_xor_sync(0xffffffffu, acc.x, 16);
    acc.y += __shfl_xor_sync(0xffffffffu, acc.y, 16);
    acc.z += __shfl_xor_sync(0xffffffffu, acc.z, 16);
    acc.w += __shfl_xor_sync(0xffffffffu, acc.w, 16);

    // ---- emb = 0.5*user + 0.5*mean ----
    const int ui   = max(soff + sz - 1, 0);
    const int urow = __ldg(&user[ui]);
    const float4 ue = ldg_el(&uw[(size_t)urow * H + 4 * q], pol);
    const float inv = 0.5f / ((float)sz + 1e-6f);
    float4 emb;
    emb.x = 0.5f * ue.x + acc.x * inv;
    emb.y = 0.5f * ue.y + acc.y * inv;
    emb.z = 0.5f * ue.z + acc.z * inv;
    emb.w = 0.5f * ue.w + acc.w * inv;

    // ---- center + L2 normalize (width-16, replicated in both halves) ----
    float v2r[2];
    v2r[0] = emb.x + emb.y + emb.z + emb.w;
    v2r[1] = emb.x*emb.x + emb.y*emb.y + emb.z*emb.z + emb.w*emb.w;
    red16<2>(v2r);
    const float mean = v2r[0] * (1.0f / H);
    const float ss   = fmaxf(v2r[1] - v2r[0] * mean, 0.0f);
    const float invn = 1.0f / fmaxf(sqrtf(ss), 1e-12f);
    float4 en;
    en.x = (emb.x - mean) * invn;
    en.y = (emb.y - mean) * invn;
    en.z = (emb.z - mean) * invn;
    en.w = (emb.w - mean) * invn;

    // ---- targets: one wave of <=5 loads per lane, one batched reduction.
    //      sum(en)==0 so dot(center(te), en) == dot(te, en). ----
    const int nt0 = min(tsz, 2 * NT);
    const int ta  = (lane < min(tsz, 32)) ? __ldg(&tgt[toff + lane]) : 0;
    float4 tr[NT];
    #pragma unroll
    for (int k = 0; k < NT; k++) {
        const int t   = 2*k + h;
        const int row = __shfl_sync(0xffffffffu, ta, t & 31);
        tr[k] = (t < nt0) ? ldg_el(&iw[(size_t)row * H + 4 * q], pol)
                          : make_float4(0.f,0.f,0.f,0.f);
    }
    float r3[3 * NT];
    #pragma unroll
    for (int k = 0; k < NT; k++) {
        const float4 te = tr[k];
        r3[3*k+0] = te.x + te.y + te.z + te.w;
        r3[3*k+1] = te.x*te.x + te.y*te.y + te.z*te.z + te.w*te.w;
        r3[3*k+2] = te.x*en.x + te.y*en.y + te.z*en.z + te.w*en.w;
    }
    red16<3 * NT>(r3);
    if (q == 0) {
        #pragma unroll
        for (int k = 0; k < NT; k++) {
            const int t = 2*k + h;
            if (t < nt0) {
                const float mt  = r3[3*k+0] * (1.0f / H);
                const float sst = fmaxf(r3[3*k+1] - r3[3*k+0] * mt, 0.0f);
                out[toff + t] = r3[3*k+2] / fmaxf(sqrtf(sst), 1e-12f);
            }
        }
    }
    // rare fallback: tsz > 10
    for (int t0 = 2 * NT; t0 < tsz; t0 += 2) {
        const int t = t0 + h;
        if (t < tsz) {
            const int row = __ldg(&tgt[toff + t]);
            const float4 te = ldg_el(&iw[(size_t)row * H + 4 * q], pol);
            float v3[3];
            v3[0] = te.x + te.y + te.z + te.w;
            v3[1] = te.x*te.x + te.y*te.y + te.z*te.z + te.w*te.w;
            v3[2] = te.x*en.x + te.y*en.y + te.z*en.z + te.w*en.w;
            red16<3>(v3);
            if (q == 0) {
                const float mt  = v3[0] * (1.0f / H);
                const float sst = fmaxf(v3[1] - v3[0] * mt, 0.0f);
                out[toff + t] = v3[2] / fmaxf(sqrtf(sst), 1e-12f);
            }
        }
    }
}

// ---------------------------------------------------------------------------
extern "C" void kernel_launch(void* const* d_in, const int* in_sizes, int n_in,
                              void* d_out, int out_size) {
    const int*   user        = (const int*)d_in[0];
    const int*   item        = (const int*)d_in[1];
    const int*   target_item = (const int*)d_in[2];
    const int*   size        = (const int*)d_in[3];
    const int*   target_size = (const int*)d_in[4];
    const float* user_weight = (const float*)d_in[5];
    const float* item_weight = (const float*)d_in[6];
    float*       out         = (float*)d_out;

    const int B = in_sizes[3];
    const int wpb  = TPB >> 5;
    const int grid = (B + wpb - 1) / wpb;

    scan_kernel<<<1, 1024>>>(size, target_size, B);
    simplex_kernel<<<grid, TPB>>>(user, item, target_item, size, target_size,
                                  user_weight, item_weight, out, B);
}

// round 11
// speedup vs baseline: 1.1210x; 1.0775x over previous
#include <cuda_runtime.h>
#include <cuda_bf16.h>
#include <cstdint>

#define MAX_B  32768
#define H      64
#define TPB    256          // 8 warps = 8 batch groups per block

__device__ int g_s32[MAX_B / 32];   // exclusive prefix of size, per 32 batches
__device__ int g_t32[MAX_B / 32];   // exclusive prefix of target_size, per 32

// ---------------------------------------------------------------------------
// Kernel 1 (scan-lite): one block, 512 threads; thread i sums elements
// [32i, 32i+32) of size/tsize, block-scans the 512 partials, writes the
// EXCLUSIVE per-group prefixes (4 KB total instead of 128 KB).
// ---------------------------------------------------------------------------
__global__ void __launch_bounds__(512)
scan_lite_kernel(const int* __restrict__ size, const int* __restrict__ tsize,
                 int B) {
    __shared__ int sw[16], tw[16];
    const int t = threadIdx.x, lane = t & 31, wid = t >> 5;
    const int ngrp = (B + 31) >> 5;          // groups of 32

    int s0 = 0, t0 = 0;
    const int e0 = t * 32;
    if (t < ngrp) {
        #pragma unroll
        for (int j = 0; j < 32; j += 4) {
            if (e0 + j + 3 < B) {
                const int4 a = *(const int4*)(size  + e0 + j);
                const int4 c = *(const int4*)(tsize + e0 + j);
                s0 += a.x + a.y + a.z + a.w;
                t0 += c.x + c.y + c.z + c.w;
            } else {
                for (int k = j; k < 32 && e0 + k < B; k++) {
                    s0 += size[e0 + k]; t0 += tsize[e0 + k];
                }
                break;
            }
        }
    }
    // warp inclusive scan
    int si = s0, ti = t0;
    #pragma unroll
    for (int o = 1; o < 32; o <<= 1) {
        const int a = __shfl_up_sync(0xffffffffu, si, o);
        const int b = __shfl_up_sync(0xffffffffu, ti, o);
        if (lane >= o) { si += a; ti += b; }
    }
    if (lane == 31) { sw[wid] = si; tw[wid] = ti; }
    __syncthreads();
    if (wid == 0 && lane < 16) {
        int a = sw[lane], b = tw[lane];
        #pragma unroll
        for (int o = 1; o < 16; o <<= 1) {
            const int x = __shfl_up_sync(0xffffu, a, o);
            const int y = __shfl_up_sync(0xffffu, b, o);
            if (lane >= o) { a += x; b += y; }
        }
        sw[lane] = a; tw[lane] = b;
    }
    __syncthreads();
    if (t < ngrp) {
        g_s32[t] = (wid ? sw[wid - 1] : 0) + si - s0;   // exclusive prefix
        g_t32[t] = (wid ? tw[wid - 1] : 0) + ti - t0;
    }
}

// ---------------------------------------------------------------------------
// helpers
// ---------------------------------------------------------------------------
__device__ __forceinline__ float4 f4add(float4 a, float4 b) {
    return make_float4(a.x + b.x, a.y + b.y, a.z + b.z, a.w + b.w);
}
__device__ __forceinline__ int pick_idx(int ia, int ib, int r) {
    const int v = __shfl_sync(0xffffffffu, ia, r & 31);
    const int w = __shfl_sync(0xffffffffu, ib, r & 31);
    return (r < 32) ? v : w;
}
template <int N>
__device__ __forceinline__ void red16(float (&v)[N]) {
    #pragma unroll
    for (int o = 8; o > 0; o >>= 1) {
        #pragma unroll
        for (int k = 0; k < N; k++)
            v[k] += __shfl_xor_sync(0xffffffffu, v[k], o);
    }
}

// ---------------------------------------------------------------------------
// Kernel 2 (round-4 champion body): one warp per batch group; 16 lanes/row
// (quad q), halves h=0/1; item loop = 8 rows / 4 independent LDG.128 per
// lane-pair iteration; serialized 2-per-iter target loop. Offsets are
// reconstructed locally from per-32 partials (one warp scan).
// ---------------------------------------------------------------------------
__global__ void __launch_bounds__(TPB)
simplex_kernel(const int*   __restrict__ user,
               const int*   __restrict__ item,
               const int*   __restrict__ tgt,
               const int*   __restrict__ size,
               const int*   __restrict__ tsize,
               const float* __restrict__ uw,
               const float* __restrict__ iw,
               float*       __restrict__ out,
               int B) {
    const int b = blockIdx.x * (TPB >> 5) + (threadIdx.x >> 5);
    if (b >= B) return;
    const int lane = threadIdx.x & 31;
    const int q    = lane & 15;
    const int h    = lane >> 4;

    // ---- reconstruct soff/toff from per-32 partials (warp scan) ----
    const int g0  = b >> 5;          // 32-batch group
    const int r   = b & 31;          // position within group
    const int gb  = g0 << 5;
    const int in_range = (gb + lane) < B;
    const int s_el = in_range ? __ldg(&size[gb + lane])  : 0;
    const int t_el = in_range ? __ldg(&tsize[gb + lane]) : 0;
    int si = s_el, ti = t_el;
    #pragma unroll
    for (int o = 1; o < 32; o <<= 1) {
        const int a = __shfl_up_sync(0xffffffffu, si, o);
        const int c = __shfl_up_sync(0xffffffffu, ti, o);
        if (lane >= o) { si += a; ti += c; }
    }
    // exclusive prefix at r, and this batch's sizes
    const int es   = __shfl_sync(0xffffffffu, si, (r > 0) ? (r - 1) : 0);
    const int et   = __shfl_sync(0xffffffffu, ti, (r > 0) ? (r - 1) : 0);
    const int soff = __ldg(&g_s32[g0]) + ((r > 0) ? es : 0);
    const int toff = __ldg(&g_t32[g0]) + ((r > 0) ? et : 0);
    const int sz   = __shfl_sync(0xffffffffu, s_el, r);
    const int tsz  = __shfl_sync(0xffffffffu, t_el, r);

    // ---- item segment sum: chunks of 64 indices, 8 rows / 4 loads per iter
    float4 acc0 = make_float4(0.f,0.f,0.f,0.f);
    float4 acc1 = make_float4(0.f,0.f,0.f,0.f);
    for (int cb = 0; cb < sz; cb += 64) {
        const int n  = min(sz - cb, 64);
        const int ia = (lane      < n) ? __ldg(&item[soff + cb + lane])      : 0;
        const int ib = (lane + 32 < n) ? __ldg(&item[soff + cb + 32 + lane]) : 0;

        int base = 0;
        for (; base + 8 <= n; base += 8) {
            const int i0 = pick_idx(ia, ib, base + 0 + h);
            const int i1 = pick_idx(ia, ib, base + 2 + h);
            const int i2 = pick_idx(ia, ib, base + 4 + h);
            const int i3 = pick_idx(ia, ib, base + 6 + h);
            const float4 v0 = __ldg((const float4*)&iw[(size_t)i0 * H + 4 * q]);
            const float4 v1 = __ldg((const float4*)&iw[(size_t)i1 * H + 4 * q]);
            const float4 v2 = __ldg((const float4*)&iw[(size_t)i2 * H + 4 * q]);
            const float4 v3 = __ldg((const float4*)&iw[(size_t)i3 * H + 4 * q]);
            acc0 = f4add(acc0, f4add(v0, v2));
            acc1 = f4add(acc1, f4add(v1, v3));
        }
        for (; base < n; base += 2) {
            const int rr = base + h;
            if (rr < n) {
                const int ii = pick_idx(ia, ib, rr);
                acc0 = f4add(acc0, __ldg((const float4*)&iw[(size_t)ii * H + 4 * q]));
            }
        }
    }
    float4 acc = f4add(acc0, acc1);
    acc.x += __shfl_xor_sync(0xffffffffu, acc.x, 16);
    acc.y += __shfl_xor_sync(0xffffffffu, acc.y, 16);
    acc.z += __shfl_xor_sync(0xffffffffu, acc.z, 16);
    acc.w += __shfl_xor_sync(0xffffffffu, acc.w, 16);

    // ---- emb = 0.5*user + 0.5*mean ----
    const int ui   = max(soff + sz - 1, 0);
    const int urow = __ldg(&user[ui]);
    const float4 ue = __ldg((const float4*)&uw[(size_t)urow * H + 4 * q]);
    const float inv = 0.5f / ((float)sz + 1e-6f);
    float4 emb;
    emb.x = 0.5f * ue.x + acc.x * inv;
    emb.y = 0.5f * ue.y + acc.y * inv;
    emb.z = 0.5f * ue.z + acc.z * inv;
    emb.w = 0.5f * ue.w + acc.w * inv;

    // ---- center + L2 normalize (width-16, replicated in both halves) ----
    float v2r[2];
    v2r[0] = emb.x + emb.y + emb.z + emb.w;
    v2r[1] = emb.x*emb.x + emb.y*emb.y + emb.z*emb.z + emb.w*emb.w;
    red16<2>(v2r);
    const float mean = v2r[0] * (1.0f / H);
    const float ss   = fmaxf(v2r[1] - v2r[0] * mean, 0.0f);
    const float invn = 1.0f / fmaxf(sqrtf(ss), 1e-12f);
    float4 en;
    en.x = (emb.x - mean) * invn;
    en.y = (emb.y - mean) * invn;
    en.z = (emb.z - mean) * invn;
    en.w = (emb.w - mean) * invn;

    // ---- targets: two per iteration (one per half). sum(en)==0 so
    //      dot(center(te), en) == dot(te, en). ----
    for (int cb = 0; cb < tsz; cb += 32) {
        const int n  = min(tsz - cb, 32);
        const int ta = (lane < n) ? __ldg(&tgt[toff + cb + lane]) : 0;
        for (int base = 0; base < n; base += 2) {
            const int t = base + h;
            if (t < n) {
                const int row = __shfl_sync(0xffffffffu, ta, t);
                const float4 te = __ldg((const float4*)&iw[(size_t)row * H + 4 * q]);
                float v3[3];
                v3[0] = te.x + te.y + te.z + te.w;
                v3[1] = te.x*te.x + te.y*te.y + te.z*te.z + te.w*te.w;
                v3[2] = te.x*en.x + te.y*en.y + te.z*en.z + te.w*en.w;
                red16<3>(v3);
                if (q == 0) {
                    const float mt  = v3[0] * (1.0f / H);
                    const float sst = fmaxf(v3[1] - v3[0] * mt, 0.0f);
                    out[toff + cb + t] = v3[2] / fmaxf(sqrtf(sst), 1e-12f);
                }
            }
        }
    }
}

// ---------------------------------------------------------------------------
extern "C" void kernel_launch(void* const* d_in, const int* in_sizes, int n_in,
                              void* d_out, int out_size) {
    const int*   user        = (const int*)d_in[0];
    const int*   item        = (const int*)d_in[1];
    const int*   target_item = (const int*)d_in[2];
    const int*   size        = (const int*)d_in[3];
    const int*   target_size = (const int*)d_in[4];
    const float* user_weight = (const float*)d_in[5];
    const float* item_weight = (const float*)d_in[6];
    float*       out         = (float*)d_out;

    const int B = in_sizes[3];
    const int wpb  = TPB >> 5;
    const int grid = (B + wpb - 1) / wpb;

    scan_lite_kernel<<<1, 512>>>(size, target_size, B);
    simplex_kernel<<<grid, TPB>>>(user, item, target_item, size, target_size,
                                  user_weight, item_weight, out, B);
}

// round 12
// speedup vs baseline: 1.2120x; 1.0812x over previous
#include <cuda_runtime.h>
#include <cuda_bf16.h>
#include <cstdint>

#define MAX_B  32768
#define H      64
#define TPB    256          // 8 warps = 8 batch groups per block

__device__ int g_s32[MAX_B / 32];   // exclusive prefix of size, per 32 batches
__device__ int g_t32[MAX_B / 32];   // exclusive prefix of target_size, per 32

// ---------------------------------------------------------------------------
// Kernel 1 (scan-lite): one block, 512 threads; thread i sums elements
// [32i, 32i+32) of size/tsize, block-scans the 512 partials, writes the
// EXCLUSIVE per-group prefixes (4 KB total instead of 128 KB).
// ---------------------------------------------------------------------------
__global__ void __launch_bounds__(512)
scan_lite_kernel(const int* __restrict__ size, const int* __restrict__ tsize,
                 int B) {
    __shared__ int sw[16], tw[16];
    const int t = threadIdx.x, lane = t & 31, wid = t >> 5;
    const int ngrp = (B + 31) >> 5;          // groups of 32

    int s0 = 0, t0 = 0;
    const int e0 = t * 32;
    if (t < ngrp) {
        #pragma unroll
        for (int j = 0; j < 32; j += 4) {
            if (e0 + j + 3 < B) {
                const int4 a = *(const int4*)(size  + e0 + j);
                const int4 c = *(const int4*)(tsize + e0 + j);
                s0 += a.x + a.y + a.z + a.w;
                t0 += c.x + c.y + c.z + c.w;
            } else {
                for (int k = j; k < 32 && e0 + k < B; k++) {
                    s0 += size[e0 + k]; t0 += tsize[e0 + k];
                }
                break;
            }
        }
    }
    // warp inclusive scan
    int si = s0, ti = t0;
    #pragma unroll
    for (int o = 1; o < 32; o <<= 1) {
        const int a = __shfl_up_sync(0xffffffffu, si, o);
        const int b = __shfl_up_sync(0xffffffffu, ti, o);
        if (lane >= o) { si += a; ti += b; }
    }
    if (lane == 31) { sw[wid] = si; tw[wid] = ti; }
    __syncthreads();
    if (wid == 0 && lane < 16) {
        int a = sw[lane], b = tw[lane];
        #pragma unroll
        for (int o = 1; o < 16; o <<= 1) {
            const int x = __shfl_up_sync(0xffffu, a, o);
            const int y = __shfl_up_sync(0xffffu, b, o);
            if (lane >= o) { a += x; b += y; }
        }
        sw[lane] = a; tw[lane] = b;
    }
    __syncthreads();
    if (t < ngrp) {
        g_s32[t] = (wid ? sw[wid - 1] : 0) + si - s0;   // exclusive prefix
        g_t32[t] = (wid ? tw[wid - 1] : 0) + ti - t0;
    }
}

// ---------------------------------------------------------------------------
// helpers
// ---------------------------------------------------------------------------
__device__ __forceinline__ float4 f4add(float4 a, float4 b) {
    return make_float4(a.x + b.x, a.y + b.y, a.z + b.z, a.w + b.w);
}
__device__ __forceinline__ int pick_idx(int ia, int ib, int r) {
    const int v = __shfl_sync(0xffffffffu, ia, r & 31);
    const int w = __shfl_sync(0xffffffffu, ib, r & 31);
    return (r < 32) ? v : w;
}
template <int N>
__device__ __forceinline__ void red16(float (&v)[N]) {
    #pragma unroll
    for (int o = 8; o > 0; o >>= 1) {
        #pragma unroll
        for (int k = 0; k < N; k++)
            v[k] += __shfl_xor_sync(0xffffffffu, v[k], o);
    }
}

// ---------------------------------------------------------------------------
// Kernel 2 (round-4 champion body, forced to the champion's 32-reg budget):
// one warp per batch group; 16 lanes/row (quad q), halves h=0/1; item loop =
// 8 rows / 4 independent LDG.128 per lane-pair iteration; serialized
// 2-per-iter target loop. Offsets reconstructed locally from per-32 partials
// (warp scan in the preamble; any reg pressure spills there, not in the loop).
// ---------------------------------------------------------------------------
__global__ void __launch_bounds__(TPB, 8)
simplex_kernel(const int*   __restrict__ user,
               const int*   __restrict__ item,
               const int*   __restrict__ tgt,
               const int*   __restrict__ size,
               const int*   __restrict__ tsize,
               const float* __restrict__ uw,
               const float* __restrict__ iw,
               float*       __restrict__ out,
               int B) {
    const int b = blockIdx.x * (TPB >> 5) + (threadIdx.x >> 5);
    if (b >= B) return;
    const int lane = threadIdx.x & 31;
    const int q    = lane & 15;
    const int h    = lane >> 4;

    // ---- reconstruct soff/toff from per-32 partials (warp scan) ----
    const int g0  = b >> 5;          // 32-batch group
    const int r   = b & 31;          // position within group
    const int gb  = g0 << 5;
    const int in_range = (gb + lane) < B;
    const int s_el = in_range ? __ldg(&size[gb + lane])  : 0;
    const int t_el = in_range ? __ldg(&tsize[gb + lane]) : 0;
    int si = s_el, ti = t_el;
    #pragma unroll
    for (int o = 1; o < 32; o <<= 1) {
        const int a = __shfl_up_sync(0xffffffffu, si, o);
        const int c = __shfl_up_sync(0xffffffffu, ti, o);
        if (lane >= o) { si += a; ti += c; }
    }
    // exclusive prefix at r, and this batch's sizes
    const int es   = __shfl_sync(0xffffffffu, si, (r > 0) ? (r - 1) : 0);
    const int et   = __shfl_sync(0xffffffffu, ti, (r > 0) ? (r - 1) : 0);
    const int soff = __ldg(&g_s32[g0]) + ((r > 0) ? es : 0);
    const int toff = __ldg(&g_t32[g0]) + ((r > 0) ? et : 0);
    const int sz   = __shfl_sync(0xffffffffu, s_el, r);
    const int tsz  = __shfl_sync(0xffffffffu, t_el, r);

    // ---- item segment sum: chunks of 64 indices, 8 rows / 4 loads per iter
    float4 acc0 = make_float4(0.f,0.f,0.f,0.f);
    float4 acc1 = make_float4(0.f,0.f,0.f,0.f);
    for (int cb = 0; cb < sz; cb += 64) {
        const int n  = min(sz - cb, 64);
        const int ia = (lane      < n) ? __ldg(&item[soff + cb + lane])      : 0;
        const int ib = (lane + 32 < n) ? __ldg(&item[soff + cb + 32 + lane]) : 0;

        int base = 0;
        for (; base + 8 <= n; base += 8) {
            const int i0 = pick_idx(ia, ib, base + 0 + h);
            const int i1 = pick_idx(ia, ib, base + 2 + h);
            const int i2 = pick_idx(ia, ib, base + 4 + h);
            const int i3 = pick_idx(ia, ib, base + 6 + h);
            const float4 v0 = __ldg((const float4*)&iw[(size_t)i0 * H + 4 * q]);
            const float4 v1 = __ldg((const float4*)&iw[(size_t)i1 * H + 4 * q]);
            const float4 v2 = __ldg((const float4*)&iw[(size_t)i2 * H + 4 * q]);
            const float4 v3 = __ldg((const float4*)&iw[(size_t)i3 * H + 4 * q]);
            acc0 = f4add(acc0, f4add(v0, v2));
            acc1 = f4add(acc1, f4add(v1, v3));
        }
        for (; base < n; base += 2) {
            const int rr = base + h;
            if (rr < n) {
                const int ii = pick_idx(ia, ib, rr);
                acc0 = f4add(acc0, __ldg((const float4*)&iw[(size_t)ii * H + 4 * q]));
            }
        }
    }
    float4 acc = f4add(acc0, acc1);
    acc.x += __shfl_xor_sync(0xffffffffu, acc.x, 16);
    acc.y += __shfl_xor_sync(0xffffffffu, acc.y, 16);
    acc.z += __shfl_xor_sync(0xffffffffu, acc.z, 16);
    acc.w += __shfl_xor_sync(0xffffffffu, acc.w, 16);

    // ---- emb = 0.5*user + 0.5*mean ----
    const int ui   = max(soff + sz - 1, 0);
    const int urow = __ldg(&user[ui]);
    const float4 ue = __ldg((const float4*)&uw[(size_t)urow * H + 4 * q]);
    const float inv = 0.5f / ((float)sz + 1e-6f);
    float4 emb;
    emb.x = 0.5f * ue.x + acc.x * inv;
    emb.y = 0.5f * ue.y + acc.y * inv;
    emb.z = 0.5f * ue.z + acc.z * inv;
    emb.w = 0.5f * ue.w + acc.w * inv;

    // ---- center + L2 normalize (width-16, replicated in both halves) ----
    float v2r[2];
    v2r[0] = emb.x + emb.y + emb.z + emb.w;
    v2r[1] = emb.x*emb.x + emb.y*emb.y + emb.z*emb.z + emb.w*emb.w;
    red16<2>(v2r);
    const float mean = v2r[0] * (1.0f / H);
    const float ss   = fmaxf(v2r[1] - v2r[0] * mean, 0.0f);
    const float invn = 1.0f / fmaxf(sqrtf(ss), 1e-12f);
    float4 en;
    en.x = (emb.x - mean) * invn;
    en.y = (emb.y - mean) * invn;
    en.z = (emb.z - mean) * invn;
    en.w = (emb.w - mean) * invn;

    // ---- targets: two per iteration (one per half). sum(en)==0 so
    //      dot(center(te), en) == dot(te, en). ----
    for (int cb = 0; cb < tsz; cb += 32) {
        const int n  = min(tsz - cb, 32);
        const int ta = (lane < n) ? __ldg(&tgt[toff + cb + lane]) : 0;
        for (int base = 0; base < n; base += 2) {
            const int t = base + h;
            if (t < n) {
                const int row = __shfl_sync(0xffffffffu, ta, t);
                const float4 te = __ldg((const float4*)&iw[(size_t)row * H + 4 * q]);
                float v3[3];
                v3[0] = te.x + te.y + te.z + te.w;
                v3[1] = te.x*te.x + te.y*te.y + te.z*te.z + te.w*te.w;
                v3[2] = te.x*en.x + te.y*en.y + te.z*en.z + te.w*en.w;
                red16<3>(v3);
                if (q == 0) {
                    const float mt  = v3[0] * (1.0f / H);
                    const float sst = fmaxf(v3[1] - v3[0] * mt, 0.0f);
                    out[toff + cb + t] = v3[2] / fmaxf(sqrtf(sst), 1e-12f);
                }
            }
        }
    }
}

// ---------------------------------------------------------------------------
extern "C" void kernel_launch(void* const* d_in, const int* in_sizes, int n_in,
                              void* d_out, int out_size) {
    const int*   user        = (const int*)d_in[0];
    const int*   item        = (const int*)d_in[1];
    const int*   target_item = (const int*)d_in[2];
    const int*   size        = (const int*)d_in[3];
    const int*   target_size = (const int*)d_in[4];
    const float* user_weight = (const float*)d_in[5];
    const float* item_weight = (const float*)d_in[6];
    float*       out         = (float*)d_out;

    const int B = in_sizes[3];
    const int wpb  = TPB >> 5;
    const int grid = (B + wpb - 1) / wpb;

    scan_lite_kernel<<<1, 512>>>(size, target_size, B);
    simplex_kernel<<<grid, TPB>>>(user, item, target_item, size, target_size,
                                  user_weight, item_weight, out, B);
}